// round 10
// baseline (speedup 1.0000x reference)
#include <cuda_runtime.h>
#include <stdint.h>

// HierarchicalRingTopK: 3x3x3 VALID conv (120 ch) + 4-level gated top-k keep.
// x: (8,3,256,256) f32, w: (120,3,3,3) f32, b: (120,) f32 -> out: (8,120,254,254) f32
//
// FROZEN NUMERICS (rel_err == 0.0 since R4): per-channel serial fp32 FMA chain
// over 27 taps in NHWC patch order (kh, kw, c innermost) from 0, bias added as
// a separate fp32 add. Keys rotl(bits,1). Top-k: magnitude strict-> scan,
// lower index wins ties. f32x2 lanes are independent rn-FMAs (bit-identical).
//
// R9: R6 shape (1 pixel/thread, BT=128) with sEnc halved to 32 key columns.
// Levels 0-2 fit natively (n<=32); level 3 (n=64) has <=32 live channels by
// gating construction, stored at compacted slots (order-preserving), decoded
// back to channel ids via popc binary search on the gate. smem 46.2->29.8KB
// -> 5 CTAs/SM = 20 warps (was 16) on an L1-wavefront-bound kernel.

#define BT 128
#define OH 254
#define OW 254
#define PLANE (OH * OW)          // 64516
#define NPIX (8 * PLANE)         // 516128
#define NCH 120
#define NPAIR (NCH / 2)          // 60

__device__ __forceinline__ unsigned long long ffma2(unsigned long long a,
                                                    unsigned long long bb_,
                                                    unsigned long long c) {
    unsigned long long d;
    asm("fma.rn.f32x2 %0, %1, %2, %3;" : "=l"(d) : "l"(a), "l"(bb_), "l"(c));
    return d;
}
__device__ __forceinline__ unsigned long long pack2(float lo, float hi) {
    unsigned long long r;
    asm("mov.b64 %0, {%1, %2};" : "=l"(r) : "f"(lo), "f"(hi));
    return r;
}
__device__ __forceinline__ void unpack2(unsigned long long v, float& lo, float& hi) {
    asm("mov.b64 {%0, %1}, %2;" : "=f"(lo), "=f"(hi) : "l"(v));
}

// Gating: selected j -> enable bits 2j..2j+3 (mod 2n). Branch-free bit-spread.
// Validated rel_err==0.0 in R8/R9 bench. Handles the j==31 wrap for n=32.
__device__ __forceinline__ unsigned long long gate_from_sel(unsigned m, int n) {
    unsigned long long xv = m;
    xv = (xv | (xv << 16)) & 0x0000FFFF0000FFFFull;
    xv = (xv | (xv << 8 )) & 0x00FF00FF00FF00FFull;
    xv = (xv | (xv << 4 )) & 0x0F0F0F0F0F0F0F0Full;
    xv = (xv | (xv << 2 )) & 0x3333333333333333ull;
    xv = (xv | (xv << 1 )) & 0x5555555555555555ull;     // bit j -> bit 2j
    unsigned long long gg = xv | (xv << 1) | (xv << 2) | (xv << 3);
    if (n == 32 && (m >> 31)) gg |= 0x3ull;             // wrap of j=31
    const int Wn = n * 2;
    if (Wn < 64)
        gg = (gg | (gg >> Wn)) & ((1ull << Wn) - 1ull);
    return gg;
}

// Index of the n-th (0-based) set bit of v. Caller guarantees popcll(v) > n.
__device__ __forceinline__ int nth_set_bit(unsigned long long v, int n) {
    unsigned part = (unsigned)v;
    int idx = 0, c = __popc(part);
    if (n >= c) { part = (unsigned)(v >> 32); idx = 32; n -= c; }
    c = __popc(part & 0xFFFFu); if (n >= c) { idx += 16; part >>= 16; n -= c; }
    c = __popc(part & 0xFFu);   if (n >= c) { idx += 8;  part >>= 8;  n -= c; }
    c = __popc(part & 0xFu);    if (n >= c) { idx += 4;  part >>= 4;  n -= c; }
    c = __popc(part & 0x3u);    if (n >= c) { idx += 2;  part >>= 2;  n -= c; }
    c = part & 0x1u;            if (n >= c) { idx += 1; }
    return idx;
}

__global__ void __launch_bounds__(BT, 5)
hrtk_kernel(const float* __restrict__ x,
            const float* __restrict__ w,
            const float* __restrict__ b,
            float* __restrict__ out)
{
    // Pair-interleaved weights: wsh2[pr*56 + 2q+e] = w[2pr+e][q]; +54/+55 = biases.
    __shared__ float    wsh2[NPAIR * 56];    // 13440 B
    __shared__ unsigned sEnc[32 * BT];       // 16384 B (32 key columns)

    const int t = threadIdx.x;

    for (int q = t; q < NPAIR * 56; q += BT) {
        const int pr = q / 56;
        const int r  = q - pr * 56;
        wsh2[q] = (r < 54) ? w[(pr * 2 + (r & 1)) * 27 + (r >> 1)]
                           : b[pr * 2 + (r - 54)];
    }
    __syncthreads();

    const int p = blockIdx.x * BT + t;
    if (p >= NPIX) return;
    // NPIX % BT == 32: tail block keeps exactly one FULL warp -> shuffles safe.

    const int ww = p % OW;
    const int rest = p / OW;
    const int hh = rest % OH;
    const int bb = rest / OH;

    unsigned long long win2[27];
    const float* xb = x + (size_t)bb * (3 * 65536) + hh * 256 + ww;
#pragma unroll
    for (int ci = 0; ci < 3; ci++)
#pragma unroll
        for (int kh = 0; kh < 3; kh++)
#pragma unroll
            for (int kw = 0; kw < 3; kw++) {
                const float v = __ldg(xb + ci * 65536 + kh * 256 + kw);
                win2[ci * 9 + kh * 3 + kw] = pack2(v, v);
            }

    float* ob = out + (size_t)bb * (NCH * PLANE) + hh * OW + ww;

    unsigned long long gate = ~0ull;
    int base = 0;

    // ================= levels 0..2 (n = 8,16,32: native 32-column layout) ====
#pragma unroll
    for (int lvl = 0; lvl < 3; lvl++) {
        const int n = 8 << lvl;   // 8,16,32
        const int k = 2 << lvl;   // 2,4,8
        const int G = n >> 3;     // 1,2,4

        unsigned long long ugate = ~0ull;
        if (lvl > 0) {
            unsigned lo = (unsigned)gate, hi = (unsigned)(gate >> 32);
#pragma unroll
            for (int o = 16; o; o >>= 1) {
                lo |= __shfl_xor_sync(0xffffffffu, lo, o);
                hi |= __shfl_xor_sync(0xffffffffu, hi, o);
            }
            ugate = ((unsigned long long)hi << 32) | lo;
        }

        unsigned gmag[4];
#pragma unroll
        for (int g = 0; g < 4; g++) gmag[g] = 0u;

        // ---- conv + encode + zero-prefill + group-max build ----
#pragma unroll
        for (int g = 0; g < G; g++) {
            const int ib = g << 3;
            if (((ugate >> ib) & 0xFFull) == 0ull) {
#pragma unroll
                for (int j = 0; j < 8; j++) {
                    sEnc[(ib + j) * BT + t] = 0u;
                    ob[(base + ib + j) * PLANE] = 0.0f;
                }
                continue;
            }
            unsigned gm = 0u;
#pragma unroll
            for (int j2 = 0; j2 < 4; j2++) {
                const int i0 = ib + j2 * 2;
                const int pr = (base + i0) >> 1;
                const float4* wv = (const float4*)(wsh2 + pr * 56);
                float wrp[56];
#pragma unroll
                for (int z = 0; z < 14; z++) *(float4*)&wrp[4 * z] = wv[z];

                // FROZEN: Eigen/NHWC tap order, per-lane serial fp32 chain.
                unsigned long long acc = 0ull;
#pragma unroll
                for (int kh = 0; kh < 3; kh++)
#pragma unroll
                    for (int kw = 0; kw < 3; kw++)
#pragma unroll
                        for (int ci = 0; ci < 3; ci++) {
                            const int q = ci * 9 + kh * 3 + kw;
                            acc = ffma2(win2[q],
                                        *(const unsigned long long*)&wrp[2 * q],
                                        acc);
                        }
                float a0, a1;
                unpack2(acc, a0, a1);
                const float act0 = a0 + wrp[54];
                const float act1 = a1 + wrp[55];

                const unsigned b0 = __float_as_uint(act0);
                const unsigned b1 = __float_as_uint(act1);
                unsigned k0 = __funnelshift_l(b0, b0, 1);
                unsigned k1 = __funnelshift_l(b1, b1, 1);
                k0 = ((unsigned)(gate >> (i0    )) & 1u) ? k0 : 0u;
                k1 = ((unsigned)(gate >> (i0 + 1)) & 1u) ? k1 : 0u;
                sEnc[(i0    ) * BT + t] = k0;
                sEnc[(i0 + 1) * BT + t] = k1;
                ob[(base + i0    ) * PLANE] = 0.0f;
                ob[(base + i0 + 1) * PLANE] = 0.0f;
                const unsigned um0 = k0 >> 1, um1 = k1 >> 1;
                if (um0 > gm) gm = um0;          // ascending: first-wins kept
                if (um1 > gm) gm = um1;
            }
            gmag[g] = gm;
        }

        // ---- k extractions: register group-max + one 8-slot rescan ----
        unsigned selmask = 0u;
#pragma unroll 1
        for (int s = 0; s < k; s++) {
            unsigned bm = 0u;
            int bg = 0;
#pragma unroll
            for (int g = 0; g < 4; g++)
                if (g < G && gmag[g] > bm) { bm = gmag[g]; bg = g; }   // strict >
            if (!bm) break;

            unsigned m2 = 0u, ufull = 0u, found = 0u;
            int leaf = 0;
            const int gb = bg << 3;
#pragma unroll
            for (int j = 0; j < 8; j++) {
                const unsigned u = sEnc[(gb + j) * BT + t];
                const unsigned um = u >> 1;
                if (um == bm && !found) { found = 1u; leaf = j; ufull = u; }
                else if (um > m2) m2 = um;
            }
            const int mi = gb + leaf;
            ob[(base + mi) * PLANE] =
                __uint_as_float(__funnelshift_r(ufull, ufull, 1));
            sEnc[mi * BT + t] = 0u;
#pragma unroll
            for (int g = 0; g < 4; g++)
                if (g == bg) gmag[g] = m2;
            selmask |= 1u << mi;
        }

        gate = gate_from_sel(selmask, n);
        base += n;
    }

    // ================= level 3 (n=64, k=16): compacted slots (live <= 32) ====
    {
        unsigned long long ugate;
        {
            unsigned lo = (unsigned)gate, hi = (unsigned)(gate >> 32);
#pragma unroll
            for (int o = 16; o; o >>= 1) {
                lo |= __shfl_xor_sync(0xffffffffu, lo, o);
                hi |= __shfl_xor_sync(0xffffffffu, hi, o);
            }
            ugate = ((unsigned long long)hi << 32) | lo;
        }

        int slot = 0;
        unsigned gmag[4];
#pragma unroll
        for (int g = 0; g < 4; g++) gmag[g] = 0u;

#pragma unroll
        for (int g = 0; g < 8; g++) {
            const int ib = g << 3;
            if (((ugate >> ib) & 0xFFull) == 0ull) {
#pragma unroll
                for (int j = 0; j < 8; j++)
                    ob[(base + ib + j) * PLANE] = 0.0f;
                continue;
            }
#pragma unroll
            for (int j2 = 0; j2 < 4; j2++) {
                const int i0 = ib + j2 * 2;
                const int pr = (base + i0) >> 1;
                const float4* wv = (const float4*)(wsh2 + pr * 56);
                float wrp[56];
#pragma unroll
                for (int z = 0; z < 14; z++) *(float4*)&wrp[4 * z] = wv[z];

                unsigned long long acc = 0ull;
#pragma unroll
                for (int kh = 0; kh < 3; kh++)
#pragma unroll
                    for (int kw = 0; kw < 3; kw++)
#pragma unroll
                        for (int ci = 0; ci < 3; ci++) {
                            const int q = ci * 9 + kh * 3 + kw;
                            acc = ffma2(win2[q],
                                        *(const unsigned long long*)&wrp[2 * q],
                                        acc);
                        }
                float a0, a1;
                unpack2(acc, a0, a1);
                const float act0 = a0 + wrp[54];
                const float act1 = a1 + wrp[55];

                const unsigned b0 = __float_as_uint(act0);
                const unsigned b1 = __float_as_uint(act1);
                const unsigned k0 = __funnelshift_l(b0, b0, 1);
                const unsigned k1 = __funnelshift_l(b1, b1, 1);
                ob[(base + i0    ) * PLANE] = 0.0f;
                ob[(base + i0 + 1) * PLANE] = 0.0f;

                // Compacted store: only live channels consume slots (ascending
                // channel order -> slot order preserves lower-index-wins).
                if ((gate >> i0) & 1ull) {
                    sEnc[slot * BT + t] = k0;
                    const unsigned um = k0 >> 1;
                    const int sg = slot >> 3;
#pragma unroll
                    for (int gg = 0; gg < 4; gg++)
                        if (gg == sg && um > gmag[gg]) gmag[gg] = um;
                    slot++;
                }
                if ((gate >> (i0 + 1)) & 1ull) {
                    sEnc[slot * BT + t] = k1;
                    const unsigned um = k1 >> 1;
                    const int sg = slot >> 3;
#pragma unroll
                    for (int gg = 0; gg < 4; gg++)
                        if (gg == sg && um > gmag[gg]) gmag[gg] = um;
                    slot++;
                }
            }
        }
        const int L = slot;    // live count (<=32); slots >= L hold stale lvl2 keys

        // ---- 16 extractions over compacted slots ----
#pragma unroll 1
        for (int s = 0; s < 16; s++) {
            unsigned bm = 0u;
            int bg = 0;
#pragma unroll
            for (int g = 0; g < 4; g++)
                if (gmag[g] > bm) { bm = gmag[g]; bg = g; }
            if (!bm) break;

            unsigned m2 = 0u, ufull = 0u, found = 0u;
            int leaf = 0;
            const int gb = bg << 3;
#pragma unroll
            for (int j = 0; j < 8; j++) {
                const unsigned u = sEnc[(gb + j) * BT + t];
                const unsigned um = ((gb + j) < L) ? (u >> 1) : 0u;   // stale mask
                if (um == bm && !found) { found = 1u; leaf = j; ufull = u; }
                else if (um > m2) m2 = um;
            }
            const int mi = gb + leaf;
            const int ch = nth_set_bit(gate, mi);      // slot -> channel id
            ob[(base + ch) * PLANE] =
                __uint_as_float(__funnelshift_r(ufull, ufull, 1));
            sEnc[mi * BT + t] = 0u;
#pragma unroll
            for (int g = 0; g < 4; g++)
                if (g == bg) gmag[g] = m2;
        }
    }
}

extern "C" void kernel_launch(void* const* d_in, const int* in_sizes, int n_in,
                              void* d_out, int out_size)
{
    const float* x = (const float*)d_in[0];
    const float* w = (const float*)d_in[1];
    const float* b = (const float*)d_in[2];
    float* out = (float*)d_out;

    const int grid = (NPIX + BT - 1) / BT;
    hrtk_kernel<<<grid, BT>>>(x, w, b, out);
}

// round 12
// speedup vs baseline: 1.1795x; 1.1795x over previous
#include <cuda_runtime.h>
#include <stdint.h>

// HierarchicalRingTopK: 3x3x3 VALID conv (120 ch) + 4-level gated top-k keep.
// x: (8,3,256,256) f32, w: (120,3,3,3) f32, b: (120,) f32 -> out: (8,120,254,254) f32
//
// FROZEN NUMERICS (rel_err == 0.0 since R4): per-channel serial fp32 FMA chain
// over 27 taps in NHWC patch order (kh, kw, c innermost) from 0, bias added as
// a separate fp32 add. Keys rotl(bits,1). Top-k: magnitude strict-> scan,
// lower index wins ties. f32x2 lanes are independent rn-FMAs (bit-identical).
//
// R11 = R10 (R6 dataflow at BT=160, dynamic sEnc, 4 CTAs/SM = 20 warps) plus
// the required cudaFuncSetAttribute(MaxDynamicSharedMemorySize) opt-in that
// R10 omitted (54.4KB/CTA > default 48KB budget -> launch failed in capture).

#define BT 160
#define OH 254
#define OW 254
#define PLANE (OH * OW)          // 64516
#define NPIX (8 * PLANE)         // 516128
#define NCH 120
#define NPAIR (NCH / 2)          // 60
#define ENC_BYTES (64 * BT * 4)  // 40960 (dynamic smem)

__device__ __forceinline__ unsigned long long ffma2(unsigned long long a,
                                                    unsigned long long bb_,
                                                    unsigned long long c) {
    unsigned long long d;
    asm("fma.rn.f32x2 %0, %1, %2, %3;" : "=l"(d) : "l"(a), "l"(bb_), "l"(c));
    return d;
}
__device__ __forceinline__ unsigned long long pack2(float lo, float hi) {
    unsigned long long r;
    asm("mov.b64 %0, {%1, %2};" : "=l"(r) : "f"(lo), "f"(hi));
    return r;
}
__device__ __forceinline__ void unpack2(unsigned long long v, float& lo, float& hi) {
    asm("mov.b64 {%0, %1}, %2;" : "=f"(lo), "=f"(hi) : "l"(v));
}

// Gating: selected j -> enable bits 2j..2j+3 (mod 2n). Branch-free bit-spread.
// Validated rel_err==0.0 in R8/R9. Handles the j==31 wrap for n=32.
__device__ __forceinline__ unsigned long long gate_from_sel(unsigned m, int n) {
    unsigned long long xv = m;
    xv = (xv | (xv << 16)) & 0x0000FFFF0000FFFFull;
    xv = (xv | (xv << 8 )) & 0x00FF00FF00FF00FFull;
    xv = (xv | (xv << 4 )) & 0x0F0F0F0F0F0F0F0Full;
    xv = (xv | (xv << 2 )) & 0x3333333333333333ull;
    xv = (xv | (xv << 1 )) & 0x5555555555555555ull;     // bit j -> bit 2j
    unsigned long long gg = xv | (xv << 1) | (xv << 2) | (xv << 3);
    if (n == 32 && (m >> 31)) gg |= 0x3ull;             // wrap of j=31
    const int Wn = n * 2;
    if (Wn < 64)
        gg = (gg | (gg >> Wn)) & ((1ull << Wn) - 1ull);
    return gg;
}

__global__ void __launch_bounds__(BT, 4)
hrtk_kernel(const float* __restrict__ x,
            const float* __restrict__ w,
            const float* __restrict__ b,
            float* __restrict__ out)
{
    // Pair-interleaved weights: wsh2[pr*56 + 2q+e] = w[2pr+e][q]; +54/+55 = biases.
    __shared__ float wsh2[NPAIR * 56];               // 13440 B (static)
    extern __shared__ unsigned sEnc[];               // 64 key columns x BT (dynamic)

    const int t = threadIdx.x;

    for (int q = t; q < NPAIR * 56; q += BT) {
        const int pr = q / 56;
        const int r  = q - pr * 56;
        wsh2[q] = (r < 54) ? w[(pr * 2 + (r & 1)) * 27 + (r >> 1)]
                           : b[pr * 2 + (r - 54)];
    }
    __syncthreads();

    const int p = blockIdx.x * BT + t;
    if (p >= NPIX) return;
    // NPIX = 160*3225 + 128: tail block keeps warps 0-3 fully live, warp 4
    // exits whole -> full-mask shuffles safe in every surviving warp.

    const int ww = p % OW;
    const int rest = p / OW;
    const int hh = rest % OH;
    const int bb = rest / OH;

    unsigned long long win2[27];
    const float* xb = x + (size_t)bb * (3 * 65536) + hh * 256 + ww;
#pragma unroll
    for (int ci = 0; ci < 3; ci++)
#pragma unroll
        for (int kh = 0; kh < 3; kh++)
#pragma unroll
            for (int kw = 0; kw < 3; kw++) {
                const float v = __ldg(xb + ci * 65536 + kh * 256 + kw);
                win2[ci * 9 + kh * 3 + kw] = pack2(v, v);
            }

    float* ob = out + (size_t)bb * (NCH * PLANE) + hh * OW + ww;

    unsigned long long gate = ~0ull;
    int base = 0;

#pragma unroll
    for (int lvl = 0; lvl < 4; lvl++) {
        const int n = 8 << lvl;   // 8,16,32,64
        const int k = 2 << lvl;   // 2,4,8,16
        const int G = n >> 3;     // groups of 8 channels

        // Warp-union of gates (uniform liveness for dead-group skip).
        unsigned long long ugate = ~0ull;
        if (lvl > 0) {
            unsigned lo = (unsigned)gate, hi = (unsigned)(gate >> 32);
#pragma unroll
            for (int o = 16; o; o >>= 1) {
                lo |= __shfl_xor_sync(0xffffffffu, lo, o);
                hi |= __shfl_xor_sync(0xffffffffu, hi, o);
            }
            ugate = ((unsigned long long)hi << 32) | lo;
        }

        unsigned gmag[8];
#pragma unroll
        for (int g = 0; g < 8; g++) gmag[g] = 0u;

        // ---- conv + encode + zero-prefill + group-max build ----
#pragma unroll
        for (int g = 0; g < G; g++) {
            const int ib = g << 3;
            unsigned gm = 0u;
            if (((ugate >> ib) & 0xFFull) == 0ull) {
#pragma unroll
                for (int j = 0; j < 8; j++) {
                    sEnc[(ib + j) * BT + t] = 0u;
                    ob[(base + ib + j) * PLANE] = 0.0f;
                }
            } else {
#pragma unroll
                for (int j2 = 0; j2 < 4; j2++) {            // 4 channel-pairs
                    const int i0 = ib + j2 * 2;
                    const int pr = (base + i0) >> 1;
                    const float4* wv = (const float4*)(wsh2 + pr * 56);
                    float wrp[56];
#pragma unroll
                    for (int z = 0; z < 14; z++) *(float4*)&wrp[4 * z] = wv[z];

                    // FROZEN: Eigen/NHWC tap order, per-lane serial fp32 chain.
                    unsigned long long acc = 0ull;
#pragma unroll
                    for (int kh = 0; kh < 3; kh++)
#pragma unroll
                        for (int kw = 0; kw < 3; kw++)
#pragma unroll
                            for (int ci = 0; ci < 3; ci++) {
                                const int q = ci * 9 + kh * 3 + kw;
                                acc = ffma2(win2[q],
                                            *(const unsigned long long*)&wrp[2 * q],
                                            acc);
                            }
                    float a0, a1;
                    unpack2(acc, a0, a1);
                    const float act0 = a0 + wrp[54];
                    const float act1 = a1 + wrp[55];

                    const unsigned b0 = __float_as_uint(act0);
                    const unsigned b1 = __float_as_uint(act1);
                    unsigned k0 = __funnelshift_l(b0, b0, 1);
                    unsigned k1 = __funnelshift_l(b1, b1, 1);
                    k0 = ((unsigned)(gate >> (i0    )) & 1u) ? k0 : 0u;
                    k1 = ((unsigned)(gate >> (i0 + 1)) & 1u) ? k1 : 0u;
                    sEnc[(i0    ) * BT + t] = k0;
                    sEnc[(i0 + 1) * BT + t] = k1;
                    ob[(base + i0    ) * PLANE] = 0.0f;
                    ob[(base + i0 + 1) * PLANE] = 0.0f;
                    const unsigned um0 = k0 >> 1, um1 = k1 >> 1;
                    if (um0 > gm) gm = um0;                  // ascending order:
                    if (um1 > gm) gm = um1;                  // first-wins kept
                }
            }
            gmag[g] = gm;
        }

        // ---- k extractions: register group-max scan + one 8-slot rescan ----
        unsigned selmask = 0u;
#pragma unroll 1
        for (int s = 0; s < k; s++) {
            unsigned bm = 0u;
            int bg = 0;
#pragma unroll
            for (int g = 0; g < 8; g++)
                if (g < G && gmag[g] > bm) { bm = gmag[g]; bg = g; }  // strict >
            if (!bm) break;                       // all remaining keys are zero

            unsigned m2 = 0u, ufull = 0u, found = 0u;
            int leaf = 0;
            const int gb = bg << 3;
#pragma unroll
            for (int j = 0; j < 8; j++) {
                const unsigned u = sEnc[(gb + j) * BT + t];
                const unsigned um = u >> 1;
                if (um == bm && !found) { found = 1u; leaf = j; ufull = u; }
                else if (um > m2) m2 = um;
            }
            const int mi = gb + leaf;
            ob[(base + mi) * PLANE] =
                __uint_as_float(__funnelshift_r(ufull, ufull, 1));
            sEnc[mi * BT + t] = 0u;
#pragma unroll
            for (int g = 0; g < 8; g++)
                if (g == bg) gmag[g] = m2;
            selmask |= 1u << mi;
        }

        if (lvl < 3)
            gate = gate_from_sel(selmask, n);
        base += n;
    }
}

extern "C" void kernel_launch(void* const* d_in, const int* in_sizes, int n_in,
                              void* d_out, int out_size)
{
    const float* x = (const float*)d_in[0];
    const float* w = (const float*)d_in[1];
    const float* b = (const float*)d_in[2];
    float* out = (float*)d_out;

    static int smem_ok = 0;
    if (!smem_ok) {
        cudaFuncSetAttribute(hrtk_kernel,
                             cudaFuncAttributeMaxDynamicSharedMemorySize,
                             ENC_BYTES);
        smem_ok = 1;
    }

    const int grid = (NPIX + BT - 1) / BT;
    hrtk_kernel<<<grid, BT, ENC_BYTES>>>(x, w, b, out);
}